// round 7
// baseline (speedup 1.0000x reference)
#include <cuda_runtime.h>

// out[r, c] = x[r, c] * weight[c]   for x: [32768, 1024] fp32, weight: [1024] fp32
//
// R7: persistent single-wave kernel WITH double-buffered pipelining.
// R6 failed because each chunk boundary drained the load->store round-trip
// (~577 cyc) with nothing else in flight. Fix: 2-deep register double-buffer;
// next chunk's 4 loads issue BEFORE current chunk's stores, keeping ~8 loads
// in flight per thread continuously. 740 CTAs = 148 SMs x 5 resident,
// no wave transitions, no repeated prologues.

static constexpr int ROWS = 32768;
static constexpr int COLS = 1024;
static constexpr unsigned N_VEC4 = (unsigned)ROWS * (COLS / 4);    // 8,388,608
static constexpr int THREADS = 256;
static constexpr int VEC = 4;                                      // per chunk
static constexpr unsigned CHUNK_VEC4 = THREADS * VEC;              // 1024
static constexpr unsigned N_CHUNKS = N_VEC4 / CHUNK_VEC4;          // 8192
static constexpr int BLOCKS = 740;                                 // 148 x 5
static constexpr int COLS_VEC4 = COLS / 4;                         // 256
static_assert(N_CHUNKS * CHUNK_VEC4 == N_VEC4, "exact cover");

__global__ __launch_bounds__(THREADS)
void diag_weight_kernel(const float4* __restrict__ x,
                        const float4* __restrict__ w,
                        float4* __restrict__ out) {
    const unsigned tid = threadIdx.x;

    // Chunk bases are multiples of 1024, so every index this thread touches
    // is congruent to tid (mod 256): one cached weight load for all chunks.
    const float4 vw = w[tid];

    unsigned c = blockIdx.x;            // first chunk (always < N_CHUNKS)

    float4 buf[2][VEC];
    unsigned cur = 0;

    // Prologue: front-batch first chunk's loads.
    {
        const unsigned base = c * CHUNK_VEC4 + tid;
#pragma unroll
        for (int i = 0; i < VEC; i++)
            buf[0][i] = __ldcs(&x[base + (unsigned)i * THREADS]);
    }

    // Steady state: prefetch chunk (c+stride) BEFORE storing chunk c, so the
    // store's data-wait overlaps the prefetch's DRAM latency.
    for (;;) {
        const unsigned next = c + (unsigned)BLOCKS;
        const bool has_next = next < N_CHUNKS;

        if (has_next) {
            const unsigned nbase = next * CHUNK_VEC4 + tid;
#pragma unroll
            for (int i = 0; i < VEC; i++)
                buf[cur ^ 1][i] = __ldcs(&x[nbase + (unsigned)i * THREADS]);
        }

        const unsigned base = c * CHUNK_VEC4 + tid;
#pragma unroll
        for (int i = 0; i < VEC; i++) {
            float4 r;
            r.x = buf[cur][i].x * vw.x;
            r.y = buf[cur][i].y * vw.y;
            r.z = buf[cur][i].z * vw.z;
            r.w = buf[cur][i].w * vw.w;
            __stcs(&out[base + (unsigned)i * THREADS], r);
        }

        if (!has_next) break;
        c = next;
        cur ^= 1;
    }
}

extern "C" void kernel_launch(void* const* d_in, const int* in_sizes, int n_in,
                              void* d_out, int out_size) {
    const float4* x = (const float4*)d_in[0];   // [32768, 1024] fp32
    const float4* w = (const float4*)d_in[1];   // [1024] fp32
    float4* out = (float4*)d_out;

    diag_weight_kernel<<<BLOCKS, THREADS>>>(x, w, out);
}

// round 8
// speedup vs baseline: 1.2255x; 1.2255x over previous
#include <cuda_runtime.h>

// out[r, c] = x[r, c] * weight[c]   for x: [32768, 1024] fp32, weight: [1024] fp32
//
// FINAL (= R5, best of 7 rounds at 43.49us): pure HBM-streaming kernel at the
// machine roofline. In-window ~36us for 268 MB = ~7.5 TB/s (~94% of spec);
// timed = in-window + ~7.8us fixed graph-replay overhead.
//
// Verdicts from the session:
// - one-shot fine-grained CTAs WIN: HW overlaps dying CTAs' store-drain with
//   fresh CTAs' front-batched loads for free (R2/R5 vs R3/R4).
// - persistent kernels LOSE: chunk-boundary drains (R6) and the register
//   double-buffer fix got demoted to local memory (R7, regs=32, L1=57%).
// - MLP=8 front-batched + __ldcs/__stcs streaming hints: best measured combo.

static constexpr int ROWS = 32768;
static constexpr int COLS = 1024;
static constexpr unsigned N_VEC4 = (unsigned)ROWS * (COLS / 4);   // 8,388,608
static constexpr int THREADS = 128;
static constexpr int VEC_PER_THREAD = 8;
static constexpr unsigned CHUNK_VEC4 = THREADS * VEC_PER_THREAD;  // 1024
static constexpr int BLOCKS = (int)(N_VEC4 / CHUNK_VEC4);         // 8192
static constexpr int COLS_VEC4 = COLS / 4;                        // 256
static_assert((unsigned)BLOCKS * CHUNK_VEC4 == N_VEC4, "exact cover");

__global__ __launch_bounds__(THREADS)
void diag_weight_kernel(const float4* __restrict__ x,
                        const float4* __restrict__ w,
                        float4* __restrict__ out) {
    const unsigned tid = threadIdx.x;
    const unsigned base = blockIdx.x * CHUNK_VEC4 + tid;

    // Column vec-index of iteration i is (base + i*128) mod 256: chunk bases
    // are multiples of 1024, so it alternates tid / tid+128. Two cached
    // weight loads (4 KiB table, L1-resident) cover all 8 iterations.
    const float4 vw0 = w[tid];          // even iterations
    const float4 vw1 = w[tid + 128];    // odd iterations

    float4 vx[VEC_PER_THREAD];

    // Front-batch all 8 streaming loads (MLP burst = 8 per thread).
#pragma unroll
    for (int i = 0; i < VEC_PER_THREAD; i++) {
        vx[i] = __ldcs(&x[base + (unsigned)i * THREADS]);
    }

#pragma unroll
    for (int i = 0; i < VEC_PER_THREAD; i++) {
        const float4 vw = (i & 1) ? vw1 : vw0;
        float4 r;
        r.x = vx[i].x * vw.x;
        r.y = vx[i].y * vw.y;
        r.z = vx[i].z * vw.z;
        r.w = vx[i].w * vw.w;
        __stcs(&out[base + (unsigned)i * THREADS], r);
    }
}

extern "C" void kernel_launch(void* const* d_in, const int* in_sizes, int n_in,
                              void* d_out, int out_size) {
    const float4* x = (const float4*)d_in[0];   // [32768, 1024] fp32
    const float4* w = (const float4*)d_in[1];   // [1024] fp32
    float4* out = (float4*)d_out;

    diag_weight_kernel<<<BLOCKS, THREADS>>>(x, w, out);
}

// round 9
// speedup vs baseline: 1.2273x; 1.0015x over previous
#include <cuda_runtime.h>

// out[r, c] = x[r, c] * weight[c]   for x: [32768, 1024] fp32, weight: [1024] fp32
//
// FINAL — R2 configuration, best measured point of the session
// (43.52us timed, 35.74us in-window = 7.5 TB/s ~ 94% of HBM spec).
//
// Session evidence (8 rounds):
// - Traffic floor: 128 MiB read + 128 MiB write, irreducible (exact fp32 op).
// - One-shot fine-grained CTAs win: HW overlaps dying CTAs' store drain with
//   fresh CTAs' front-batched loads for free (R2/R5 vs R3/R4 fat CTAs).
// - Persistent kernels lose: chunk-boundary drains (R6, -8%), and the
//   register double-buffer fix demoted to local memory (R7, -19%).
// - Occupancy 32%..77% and MLP 4..8 both move bandwidth by <2%: the DRAM
//   sink, not request supply, is the binding constraint.
// - Run-to-run noise +-0.4us; all 43.5-45.0us configs are the same roofline.

static constexpr int ROWS = 32768;
static constexpr int COLS = 1024;
static constexpr unsigned N_VEC4 = (unsigned)ROWS * (COLS / 4);   // 8,388,608
static constexpr int THREADS = 256;
static constexpr int VEC_PER_THREAD = 8;
static constexpr int BLOCKS = (int)(N_VEC4 / (THREADS * VEC_PER_THREAD)); // 4096
static constexpr int COLS_VEC4 = COLS / 4;                        // 256
static_assert(THREADS == COLS_VEC4, "weight-hoist relies on THREADS == COLS/4");
static_assert((unsigned)BLOCKS * THREADS * VEC_PER_THREAD == N_VEC4, "exact cover");

__global__ __launch_bounds__(THREADS)
void diag_weight_kernel(const float4* __restrict__ x,
                        const float4* __restrict__ w,
                        float4* __restrict__ out) {
    const unsigned tid = threadIdx.x;
    // Block covers a contiguous span of THREADS*VEC_PER_THREAD float4s;
    // iteration i is offset by i*THREADS (fully coalesced).
    const unsigned base = blockIdx.x * (unsigned)(THREADS * VEC_PER_THREAD) + tid;

    // One weight vector per thread: every index this thread touches is
    // congruent to tid (mod 256). Cached load, 4 KiB table -> L1-resident.
    const float4 vw = w[tid];

    float4 vx[VEC_PER_THREAD];

    // Front-batch all 8 streaming loads (MLP burst = 8 per thread; x is
    // single-touch, 256 MB >> 126 MB L2, so evict-first).
#pragma unroll
    for (int i = 0; i < VEC_PER_THREAD; i++) {
        vx[i] = __ldcs(&x[base + (unsigned)i * THREADS]);
    }

#pragma unroll
    for (int i = 0; i < VEC_PER_THREAD; i++) {
        float4 r;
        r.x = vx[i].x * vw.x;
        r.y = vx[i].y * vw.y;
        r.z = vx[i].z * vw.z;
        r.w = vx[i].w * vw.w;
        __stcs(&out[base + (unsigned)i * THREADS], r);
    }
}

extern "C" void kernel_launch(void* const* d_in, const int* in_sizes, int n_in,
                              void* d_out, int out_size) {
    const float4* x = (const float4*)d_in[0];   // [32768, 1024] fp32
    const float4* w = (const float4*)d_in[1];   // [1024] fp32
    float4* out = (float4*)d_out;

    diag_weight_kernel<<<BLOCKS, THREADS>>>(x, w, out);
}